// round 1
// baseline (speedup 1.0000x reference)
#include <cuda_runtime.h>

#define B_  128
#define L_  200
#define NT  25600      // B_*L_
#define D_  128
#define M_  64

// ---------------- scratch (device globals; no allocation allowed) ----------
__device__ float g_w[NT * M_];      // softmax weights      (B,L,64)
__device__ float g_e[NT * D_];      // erase gate           (B,L,128)
__device__ float g_a[NT * D_];      // add vector           (B,L,128)
__device__ float g_k[NT * D_];      // gathered k           (B,L,128)
__device__ float g_reads[NT * D_];  // scan reads           (B,L,128)
__device__ float g_diff[NT];        // question difficulty  (B,L)

__device__ __forceinline__ float sigmoidf_(float x) {
    return 1.0f / (1.0f + __expf(-x));
}

// XOR swizzle for conflict-free LDS.128: element (row, col) of a row-major
// [R x W] tile; 16B groups within a row are XOR-shuffled by (row & 7).
__device__ __forceinline__ int swz(int row, int col, int Wlog2) {
    return (row << Wlog2) + (((col >> 2) ^ (row & 7)) << 2) + (col & 3);
}

// ============================================================================
// Kernel A: per-row gather + w(softmax) + e + a + diff
// grid 148, 256 threads, ~166KB dynamic smem
// ============================================================================
__global__ void __launch_bounds__(256) kernelA(
    const int*   __restrict__ q,    const int*   __restrict__ rsel,
    const float* __restrict__ k_emb, const float* __restrict__ v_emb,
    const float* __restrict__ Mk,
    const float* __restrict__ e_W,  const float* __restrict__ e_b,
    const float* __restrict__ a_W,  const float* __restrict__ a_b,
    const float* __restrict__ df_W, const float* __restrict__ df_b)
{
    extern __shared__ float sm[];
    float* Mk_s   = sm;                    // 64*128
    float* eW_s   = Mk_s + 64 * 128;       // 128*128
    float* aW_s   = eW_s + 128 * 128;      // 128*128
    float* dfW_s  = aW_s + 128 * 128;      // 128
    float* k_s    = dfW_s + 128;           // 4*128
    float* v_s    = k_s + 512;             // 4*128
    float* logit_s = v_s + 512;            // 4*64

    const int tid = threadIdx.x;

    for (int i = tid; i < 64 * 128; i += 256) {
        int row = i >> 7, col = i & 127;
        Mk_s[swz(row, col, 7)] = Mk[i];
    }
    for (int i = tid; i < 128 * 128; i += 256) {
        int row = i >> 7, col = i & 127;
        int s = swz(row, col, 7);
        eW_s[s] = e_W[i];
        aW_s[s] = a_W[i];
    }
    if (tid < 128) dfW_s[tid] = df_W[tid];
    __syncthreads();

    const float dfb = df_b[0];
    const float4* Mk4 = (const float4*)Mk_s;
    const float4* eW4 = (const float4*)eW_s;
    const float4* aW4 = (const float4*)aW_s;

    for (int g = blockIdx.x; g < NT / 4; g += gridDim.x) {
        const int base = g * 4;

        // gather k, build v, spill k to global
        for (int i = tid; i < 512; i += 256) {
            int rl = i >> 7, d = i & 127;
            int row = base + rl;
            int qi = q[row];
            float kv = k_emb[qi * 128 + d];
            k_s[i] = kv;
            v_s[i] = kv + v_emb[rsel[row] * 128 + d];
            g_k[row * 128 + d] = kv;
        }
        __syncthreads();

        // logits: thread = (row lr, m). Mk swizzled-read, k broadcast.
        {
            int lr = tid >> 6, m = tid & 63;
            const float4* k4 = (const float4*)(k_s + (lr << 7));
            const int mb = m & 7;
            float acc = 0.f;
            #pragma unroll
            for (int dd = 0; dd < 32; dd++) {
                float4 kk = k4[dd];
                float4 mm = Mk4[(m << 5) + (dd ^ mb)];
                acc += kk.x * mm.x + kk.y * mm.y + kk.z * mm.z + kk.w * mm.w;
            }
            logit_s[(lr << 6) + m] = acc;
        }

        // e & a: thread = (row, d0) and (row, d0+64); v broadcast, weights swizzled
        {
            int row = tid >> 6, d0 = tid & 63, d1 = d0 + 64;
            const float4* v4 = (const float4*)(v_s + (row << 7));
            const int db = d0 & 7;   // == d1 & 7
            float ae0 = 0.f, aa0 = 0.f, ae1 = 0.f, aa1 = 0.f;
            #pragma unroll
            for (int jj = 0; jj < 32; jj++) {
                float4 vv = v4[jj];
                int s0 = (d0 << 5) + (jj ^ db);
                int s1 = (d1 << 5) + (jj ^ db);
                float4 w0 = eW4[s0];
                ae0 += vv.x * w0.x + vv.y * w0.y + vv.z * w0.z + vv.w * w0.w;
                float4 x0 = aW4[s0];
                aa0 += vv.x * x0.x + vv.y * x0.y + vv.z * x0.z + vv.w * x0.w;
                float4 w1 = eW4[s1];
                ae1 += vv.x * w1.x + vv.y * w1.y + vv.z * w1.z + vv.w * w1.w;
                float4 x1 = aW4[s1];
                aa1 += vv.x * x1.x + vv.y * x1.y + vv.z * x1.z + vv.w * x1.w;
            }
            int grow = (base + row) * 128;
            g_e[grow + d0] = sigmoidf_(ae0 + e_b[d0]);
            g_e[grow + d1] = sigmoidf_(ae1 + e_b[d1]);
            g_a[grow + d0] = tanhf(aa0 + a_b[d0]);
            g_a[grow + d1] = tanhf(aa1 + a_b[d1]);
        }
        __syncthreads();

        const int wid = tid >> 5, lane = tid & 31;
        if (wid < 4) {
            // softmax of logits row `wid` (64 values, 2 per lane)
            float x0 = logit_s[(wid << 6) + lane];
            float x1 = logit_s[(wid << 6) + 32 + lane];
            float mx = fmaxf(x0, x1);
            #pragma unroll
            for (int o = 16; o; o >>= 1) mx = fmaxf(mx, __shfl_xor_sync(~0u, mx, o));
            float e0 = __expf(x0 - mx), e1 = __expf(x1 - mx);
            float s = e0 + e1;
            #pragma unroll
            for (int o = 16; o; o >>= 1) s += __shfl_xor_sync(~0u, s, o);
            float inv = 1.f / s;
            int gw = (base + wid) * 64;
            g_w[gw + lane]      = e0 * inv;
            g_w[gw + 32 + lane] = e1 * inv;
        } else {
            // que_diff for row wid-4
            int row = wid - 4;
            const float* kp = k_s + (row << 7);
            float acc = kp[lane]      * dfW_s[lane]
                      + kp[lane + 32] * dfW_s[lane + 32]
                      + kp[lane + 64] * dfW_s[lane + 64]
                      + kp[lane + 96] * dfW_s[lane + 96];
            #pragma unroll
            for (int o = 16; o; o >>= 1) acc += __shfl_xor_sync(~0u, acc, o);
            if (lane == 0) g_diff[base + row] = tanhf(acc + dfb);
        }
        __syncthreads();
    }
}

// ============================================================================
// Kernel B: sequential memory scan, 1 block per batch element.
// thread = (m-half h, column d); Mv state in registers (32 floats/thread).
// ============================================================================
__global__ void __launch_bounds__(256) kernelB(const float* __restrict__ Mv0)
{
    __shared__ float w_s[2][64];
    __shared__ float part_s[2][256];

    const int tid = threadIdx.x;
    const int d = tid & 127, h = tid >> 7;
    const int b = blockIdx.x;

    const float* wrow = g_w + b * L_ * M_;
    const float* erow = g_e + b * L_ * D_;
    const float* arow = g_a + b * L_ * D_;
    float* rrow = g_reads + b * L_ * D_;

    float Mv[32];
    #pragma unroll
    for (int i = 0; i < 32; i++) Mv[i] = Mv0[(h * 32 + i) * 128 + d];

    if (tid < 64) w_s[0][tid] = wrow[tid];
    float4 wpre = make_float4(0.f, 0.f, 0.f, 0.f);
    if (tid < 16) wpre = *(const float4*)(wrow + 64 + tid * 4);
    float e_c = erow[d],        a_c = arow[d];
    float e_n = erow[128 + d],  a_n = arow[128 + d];
    __syncthreads();

    for (int t = 0; t < L_; t++) {
        const int cur = t & 1, nxt = cur ^ 1;

        float wv[32];
        #pragma unroll
        for (int i = 0; i < 8; i++) {
            float4 w4 = *(const float4*)(&w_s[cur][h * 32 + i * 4]);
            wv[i * 4] = w4.x; wv[i * 4 + 1] = w4.y;
            wv[i * 4 + 2] = w4.z; wv[i * 4 + 3] = w4.w;
        }

        float p = 0.f;
        #pragma unroll
        for (int i = 0; i < 32; i++) {
            float mv = Mv[i];
            p += wv[i] * mv;                       // read (old Mv)
            Mv[i] = mv + wv[i] * (a_c - e_c * mv); // update
        }
        part_s[cur][tid] = p;

        // stage w[t+1] (loaded 2 steps ago), prefetch w[t+2], e/a[t+2]
        if (t + 1 < L_ && tid < 16) *(float4*)(&w_s[nxt][tid * 4]) = wpre;
        if (t + 2 < L_ && tid < 16) wpre = *(const float4*)(wrow + (t + 2) * 64 + tid * 4);
        e_c = e_n; a_c = a_n;
        if (t + 2 < L_) { e_n = erow[(t + 2) * 128 + d]; a_n = arow[(t + 2) * 128 + d]; }

        __syncthreads();
        if (h == 0) rrow[t * 128 + d] = part_s[cur][d] + part_s[cur][128 + d];
    }
}

// ============================================================================
// Kernel C: f = tanh([reads,k] @ f_W^T + f_b); p = sigmoid(3*tanh(f.ab)-diff)
// grid 148, 256 threads, ~131KB smem (f_W swizzled)
// ============================================================================
__global__ void __launch_bounds__(256) kernelC(
    const float* __restrict__ f_W, const float* __restrict__ f_b,
    const float* __restrict__ ab_W, const float* __restrict__ ab_b,
    float* __restrict__ out)
{
    extern __shared__ float sm[];
    float* fW_s  = sm;               // 128*256
    float* cat_s = fW_s + 128 * 256; // 2*256
    float* red_s = cat_s + 512;      // 8

    const int tid = threadIdx.x;
    for (int i = tid; i < 128 * 256; i += 256) {
        int row = i >> 8, col = i & 255;
        fW_s[swz(row, col, 8)] = f_W[i];
    }
    __syncthreads();

    const float abb = ab_b[0];
    const float4* fW4 = (const float4*)fW_s;

    for (int g = blockIdx.x; g < NT / 2; g += gridDim.x) {
        const int base = g * 2;

        for (int i = tid; i < 512; i += 256) {
            int rl = i >> 8, c = i & 255;
            int row = base + rl;
            cat_s[i] = (c < 128) ? g_reads[row * 128 + c]
                                 : g_k[row * 128 + (c - 128)];
        }
        __syncthreads();

        const int rl = tid >> 7, dd = tid & 127;
        const float4* c4 = (const float4*)(cat_s + (rl << 8));
        const int db = dd & 7;
        float acc = 0.f;
        #pragma unroll
        for (int jj = 0; jj < 64; jj++) {
            float4 cc = c4[jj];
            float4 ww = fW4[(dd << 6) + (jj ^ db)];
            acc += cc.x * ww.x + cc.y * ww.y + cc.z * ww.z + cc.w * ww.w;
        }
        float f = tanhf(acc + f_b[dd]);
        float ps = f * ab_W[dd];
        #pragma unroll
        for (int o = 16; o; o >>= 1) ps += __shfl_xor_sync(~0u, ps, o);
        int w8 = tid >> 5;
        if ((tid & 31) == 0) red_s[w8] = ps;
        __syncthreads();
        if ((tid & 127) == 0) {
            int rb = rl * 4;
            float s = red_s[rb] + red_s[rb + 1] + red_s[rb + 2] + red_s[rb + 3];
            float ability = tanhf(s + abb);
            out[base + rl] = sigmoidf_(3.f * ability - g_diff[base + rl]);
        }
        __syncthreads();
    }
}

// ============================================================================
extern "C" void kernel_launch(void* const* d_in, const int* in_sizes, int n_in,
                              void* d_out, int out_size)
{
    (void)in_sizes; (void)n_in; (void)out_size;
    const int*   q     = (const int*)  d_in[0];
    const int*   rsel  = (const int*)  d_in[1];
    const float* k_emb = (const float*)d_in[2];
    const float* v_emb = (const float*)d_in[3];
    const float* Mk    = (const float*)d_in[4];
    const float* Mv0   = (const float*)d_in[5];
    const float* f_W   = (const float*)d_in[6];
    const float* f_b   = (const float*)d_in[7];
    const float* e_W   = (const float*)d_in[8];
    const float* e_b   = (const float*)d_in[9];
    const float* a_W   = (const float*)d_in[10];
    const float* a_b   = (const float*)d_in[11];
    const float* ab_W  = (const float*)d_in[12];
    const float* ab_b  = (const float*)d_in[13];
    const float* df_W  = (const float*)d_in[14];
    const float* df_b  = (const float*)d_in[15];
    float* out = (float*)d_out;

    const int smA = (64 * 128 + 2 * 128 * 128 + 128 + 512 + 512 + 256) * 4;
    const int smC = (128 * 256 + 512 + 8) * 4;
    cudaFuncSetAttribute(kernelA, cudaFuncAttributeMaxDynamicSharedMemorySize, smA);
    cudaFuncSetAttribute(kernelC, cudaFuncAttributeMaxDynamicSharedMemorySize, smC);

    kernelA<<<148, 256, smA>>>(q, rsel, k_emb, v_emb, Mk, e_W, e_b,
                               a_W, a_b, df_W, df_b);
    kernelB<<<128, 256>>>(Mv0);
    kernelC<<<148, 256, smC>>>(f_W, f_b, ab_W, ab_b, out);
}

// round 2
// speedup vs baseline: 1.7655x; 1.7655x over previous
#include <cuda_runtime.h>

#define B_  128
#define L_  200
#define NT  25600      // B_*L_
#define D_  128
#define M_  64

// ---------------- scratch (device globals; no allocation allowed) ----------
__device__ float g_w[NT * M_];      // softmax weights      (B,L,64)
__device__ float g_e[NT * D_];      // erase gate           (B,L,128)
__device__ float g_a[NT * D_];      // add vector           (B,L,128)
__device__ float g_k[NT * D_];      // gathered k           (B,L,128)
__device__ float g_reads[NT * D_];  // scan reads           (B,L,128)
__device__ float g_diff[NT];        // question difficulty  (B,L)

__device__ __forceinline__ float sigmoidf_(float x) {
    return 1.0f / (1.0f + __expf(-x));
}

// XOR swizzle for conflict-free strided LDS.128: element (row, col) of a
// row-major [R x (1<<Wlog2)] tile; 16B groups XOR-shuffled by (row & 7).
__device__ __forceinline__ int swz(int row, int col, int Wlog2) {
    return (row << Wlog2) + (((col >> 2) ^ (row & 7)) << 2) + (col & 3);
}

// ============================================================================
// Kernel A: 16-row tiles; gather + logits/softmax + e + a + diff
// 512 threads, ~181KB dynamic smem, 4 rows per thread in e/a (2 in logits)
// ============================================================================
__global__ void __launch_bounds__(512) kernelA(
    const int*   __restrict__ q,    const int*   __restrict__ rsel,
    const float* __restrict__ k_emb, const float* __restrict__ v_emb,
    const float* __restrict__ Mk,
    const float* __restrict__ e_W,  const float* __restrict__ e_b,
    const float* __restrict__ a_W,  const float* __restrict__ a_b,
    const float* __restrict__ df_W, const float* __restrict__ df_b)
{
    extern __shared__ float sm[];
    float* Mk_s    = sm;                    // 64*128
    float* eW_s    = Mk_s + 64 * 128;       // 128*128
    float* aW_s    = eW_s + 128 * 128;      // 128*128
    float* dfW_s   = aW_s + 128 * 128;      // 128
    float* k_s     = dfW_s + 128;           // 16*128
    float* v_s     = k_s + 2048;            // 16*128
    float* logit_s = v_s + 2048;            // 16*64
    int*   q_s     = (int*)(logit_s + 1024);// 16
    int*   r_s     = q_s + 16;              // 16

    const int tid = threadIdx.x;

    for (int i = tid; i < 64 * 128; i += 512) {
        int row = i >> 7, col = i & 127;
        Mk_s[swz(row, col, 7)] = Mk[i];
    }
    for (int i = tid; i < 128 * 128; i += 512) {
        int row = i >> 7, col = i & 127;
        int s = swz(row, col, 7);
        eW_s[s] = e_W[i];
        aW_s[s] = a_W[i];
    }
    if (tid < 128) dfW_s[tid] = df_W[tid];
    __syncthreads();

    const float dfb = df_b[0];
    // per-thread fixed-d constants for e/a epilogue
    const int dA = tid & 127;
    const float ebd = e_b[dA];
    const float abd = a_b[dA];

    const float4* Mk4 = (const float4*)Mk_s;
    const float4* eW4 = (const float4*)eW_s;
    const float4* aW4 = (const float4*)aW_s;
    const float4* v4  = (const float4*)v_s;
    const float4* k4  = (const float4*)k_s;

    for (int g = blockIdx.x; g < NT / 16; g += gridDim.x) {
        const int base = g * 16;

        if (tid < 16)      q_s[tid]      = q[base + tid];
        else if (tid < 32) r_s[tid - 16] = rsel[base + tid - 16];
        __syncthreads();

        // gather k, build v, spill k to global: 2048 elems, 4 per thread
        for (int i = tid; i < 2048; i += 512) {
            int rl = i >> 7, d = i & 127;
            float kv = k_emb[q_s[rl] * 128 + d];
            k_s[i] = kv;
            v_s[i] = kv + v_emb[r_s[rl] * 128 + d];
            g_k[(base + rl) * 128 + d] = kv;
        }
        __syncthreads();

        // ---- logits: thread = (m, rowgroup rg of 2 rows) ----
        {
            const int m = tid & 63, rg = tid >> 6;       // rg uniform per warp
            const int mb = m & 7;
            const float4* ka = k4 + (rg * 2) * 32;
            const float4* kb = ka + 32;
            float acc0 = 0.f, acc1 = 0.f;
            #pragma unroll
            for (int dd = 0; dd < 32; dd++) {
                float4 mm = Mk4[(m << 5) + (dd ^ mb)];
                float4 k0 = ka[dd];
                acc0 += k0.x * mm.x + k0.y * mm.y + k0.z * mm.z + k0.w * mm.w;
                float4 k1 = kb[dd];
                acc1 += k1.x * mm.x + k1.y * mm.y + k1.z * mm.z + k1.w * mm.w;
            }
            logit_s[(rg * 2) * 64 + m]     = acc0;
            logit_s[(rg * 2 + 1) * 64 + m] = acc1;
        }

        // ---- e & a: thread = (d, rowgroup rg of 4 rows) ----
        {
            const int d = dA, rg = tid >> 7;             // rg uniform per warp
            const int db = d & 7;
            const float4* vb = v4 + (rg * 4) * 32;
            float ae0 = 0.f, ae1 = 0.f, ae2 = 0.f, ae3 = 0.f;
            float aa0 = 0.f, aa1 = 0.f, aa2 = 0.f, aa3 = 0.f;
            #pragma unroll
            for (int jj = 0; jj < 32; jj++) {
                const int s = (d << 5) + (jj ^ db);
                float4 we = eW4[s];
                float4 wa = aW4[s];
                float4 v0 = vb[jj];
                ae0 += v0.x * we.x + v0.y * we.y + v0.z * we.z + v0.w * we.w;
                aa0 += v0.x * wa.x + v0.y * wa.y + v0.z * wa.z + v0.w * wa.w;
                float4 v1 = vb[32 + jj];
                ae1 += v1.x * we.x + v1.y * we.y + v1.z * we.z + v1.w * we.w;
                aa1 += v1.x * wa.x + v1.y * wa.y + v1.z * wa.z + v1.w * wa.w;
                float4 v2 = vb[64 + jj];
                ae2 += v2.x * we.x + v2.y * we.y + v2.z * we.z + v2.w * we.w;
                aa2 += v2.x * wa.x + v2.y * wa.y + v2.z * wa.z + v2.w * wa.w;
                float4 v3 = vb[96 + jj];
                ae3 += v3.x * we.x + v3.y * we.y + v3.z * we.z + v3.w * we.w;
                aa3 += v3.x * wa.x + v3.y * wa.y + v3.z * wa.z + v3.w * wa.w;
            }
            int r0 = (base + rg * 4) * 128 + d;
            g_e[r0]           = sigmoidf_(ae0 + ebd);
            g_e[r0 + 128]     = sigmoidf_(ae1 + ebd);
            g_e[r0 + 256]     = sigmoidf_(ae2 + ebd);
            g_e[r0 + 384]     = sigmoidf_(ae3 + ebd);
            g_a[r0]           = tanhf(aa0 + abd);
            g_a[r0 + 128]     = tanhf(aa1 + abd);
            g_a[r0 + 256]     = tanhf(aa2 + abd);
            g_a[r0 + 384]     = tanhf(aa3 + abd);
        }
        __syncthreads();

        // ---- epilogue: warp w handles row w (softmax + diff) ----
        {
            const int w = tid >> 5, lane = tid & 31;
            // softmax of 64 logits (2 per lane)
            float x0 = logit_s[(w << 6) + lane];
            float x1 = logit_s[(w << 6) + 32 + lane];
            float mx = fmaxf(x0, x1);
            #pragma unroll
            for (int o = 16; o; o >>= 1) mx = fmaxf(mx, __shfl_xor_sync(~0u, mx, o));
            float e0 = __expf(x0 - mx), e1 = __expf(x1 - mx);
            float s = e0 + e1;
            #pragma unroll
            for (int o = 16; o; o >>= 1) s += __shfl_xor_sync(~0u, s, o);
            float inv = 1.f / s;
            int gw = (base + w) * 64;
            g_w[gw + lane]      = e0 * inv;
            g_w[gw + 32 + lane] = e1 * inv;

            // que_diff for row w
            const float* kp = k_s + (w << 7);
            float acc = kp[lane]      * dfW_s[lane]
                      + kp[lane + 32] * dfW_s[lane + 32]
                      + kp[lane + 64] * dfW_s[lane + 64]
                      + kp[lane + 96] * dfW_s[lane + 96];
            #pragma unroll
            for (int o = 16; o; o >>= 1) acc += __shfl_xor_sync(~0u, acc, o);
            if (lane == 0) g_diff[base + w] = tanhf(acc + dfb);
        }
        __syncthreads();
    }
}

// ============================================================================
// Kernel B: sequential memory scan, 1 block per batch element.
// ============================================================================
__global__ void __launch_bounds__(256) kernelB(const float* __restrict__ Mv0)
{
    __shared__ float w_s[2][64];
    __shared__ float part_s[2][256];

    const int tid = threadIdx.x;
    const int d = tid & 127, h = tid >> 7;
    const int b = blockIdx.x;

    const float* wrow = g_w + b * L_ * M_;
    const float* erow = g_e + b * L_ * D_;
    const float* arow = g_a + b * L_ * D_;
    float* rrow = g_reads + b * L_ * D_;

    float Mv[32];
    #pragma unroll
    for (int i = 0; i < 32; i++) Mv[i] = Mv0[(h * 32 + i) * 128 + d];

    if (tid < 64) w_s[0][tid] = wrow[tid];
    float4 wpre = make_float4(0.f, 0.f, 0.f, 0.f);
    if (tid < 16) wpre = *(const float4*)(wrow + 64 + tid * 4);
    float e_c = erow[d],        a_c = arow[d];
    float e_n = erow[128 + d],  a_n = arow[128 + d];
    __syncthreads();

    for (int t = 0; t < L_; t++) {
        const int cur = t & 1, nxt = cur ^ 1;

        float wv[32];
        #pragma unroll
        for (int i = 0; i < 8; i++) {
            float4 w4 = *(const float4*)(&w_s[cur][h * 32 + i * 4]);
            wv[i * 4] = w4.x; wv[i * 4 + 1] = w4.y;
            wv[i * 4 + 2] = w4.z; wv[i * 4 + 3] = w4.w;
        }

        float p = 0.f;
        #pragma unroll
        for (int i = 0; i < 32; i++) {
            float mv = Mv[i];
            p += wv[i] * mv;                       // read (old Mv)
            Mv[i] = mv + wv[i] * (a_c - e_c * mv); // update
        }
        part_s[cur][tid] = p;

        if (t + 1 < L_ && tid < 16) *(float4*)(&w_s[nxt][tid * 4]) = wpre;
        if (t + 2 < L_ && tid < 16) wpre = *(const float4*)(wrow + (t + 2) * 64 + tid * 4);
        e_c = e_n; a_c = a_n;
        if (t + 2 < L_) { e_n = erow[(t + 2) * 128 + d]; a_n = arow[(t + 2) * 128 + d]; }

        __syncthreads();
        if (h == 0) rrow[t * 128 + d] = part_s[cur][d] + part_s[cur][128 + d];
    }
}

// ============================================================================
// Kernel C: 16-row tiles; f = tanh([reads,k]@f_W^T + f_b);
// p = sigmoid(3*tanh(f.ab_W + ab_b) - diff). 512 threads, 4 rows/thread.
// ============================================================================
__global__ void __launch_bounds__(512) kernelC(
    const float* __restrict__ f_W, const float* __restrict__ f_b,
    const float* __restrict__ ab_W, const float* __restrict__ ab_b,
    float* __restrict__ out)
{
    extern __shared__ float sm[];
    float* fW_s  = sm;                 // 128*256
    float* cat_s = fW_s + 128 * 256;   // 16*256
    float* red_s = cat_s + 4096;       // 16*4

    const int tid = threadIdx.x;
    for (int i = tid; i < 128 * 256; i += 512) {
        int row = i >> 8, col = i & 255;
        fW_s[swz(row, col, 8)] = f_W[i];
    }
    __syncthreads();

    const float abb = ab_b[0];
    const int dd = tid & 127, rg = tid >> 7;   // rg uniform per warp
    const float fbd = f_b[dd];
    const float abw = ab_W[dd];
    const int db = dd & 7;

    const float4* fW4 = (const float4*)fW_s;
    const float4* c4  = (const float4*)cat_s;

    for (int g = blockIdx.x; g < NT / 16; g += gridDim.x) {
        const int base = g * 16;

        for (int i = tid; i < 4096; i += 512) {
            int rl = i >> 8, c = i & 255;
            int row = base + rl;
            cat_s[i] = (c < 128) ? g_reads[row * 128 + c]
                                 : g_k[row * 128 + (c - 128)];
        }
        __syncthreads();

        const float4* cb = c4 + (rg * 4) * 64;
        float a0 = 0.f, a1 = 0.f, a2 = 0.f, a3 = 0.f;
        #pragma unroll
        for (int jj = 0; jj < 64; jj++) {
            float4 ww = fW4[(dd << 6) + (jj ^ db)];
            float4 c0 = cb[jj];
            a0 += c0.x * ww.x + c0.y * ww.y + c0.z * ww.z + c0.w * ww.w;
            float4 c1 = cb[64 + jj];
            a1 += c1.x * ww.x + c1.y * ww.y + c1.z * ww.z + c1.w * ww.w;
            float4 c2 = cb[128 + jj];
            a2 += c2.x * ww.x + c2.y * ww.y + c2.z * ww.z + c2.w * ww.w;
            float4 c3 = cb[192 + jj];
            a3 += c3.x * ww.x + c3.y * ww.y + c3.z * ww.z + c3.w * ww.w;
        }

        float p0 = tanhf(a0 + fbd) * abw;
        float p1 = tanhf(a1 + fbd) * abw;
        float p2 = tanhf(a2 + fbd) * abw;
        float p3 = tanhf(a3 + fbd) * abw;
        #pragma unroll
        for (int o = 16; o; o >>= 1) {
            p0 += __shfl_xor_sync(~0u, p0, o);
            p1 += __shfl_xor_sync(~0u, p1, o);
            p2 += __shfl_xor_sync(~0u, p2, o);
            p3 += __shfl_xor_sync(~0u, p3, o);
        }
        const int wid = tid >> 5;
        if ((tid & 31) == 0) {
            float4* rs = (float4*)(red_s + wid * 4);
            *rs = make_float4(p0, p1, p2, p3);
        }
        __syncthreads();
        if (tid < 16) {
            const int rgg = tid >> 2, rloc = tid & 3;
            float s = red_s[(rgg * 4 + 0) * 4 + rloc]
                    + red_s[(rgg * 4 + 1) * 4 + rloc]
                    + red_s[(rgg * 4 + 2) * 4 + rloc]
                    + red_s[(rgg * 4 + 3) * 4 + rloc];
            float ability = tanhf(s + abb);
            out[base + tid] = sigmoidf_(3.f * ability - g_diff[base + tid]);
        }
        __syncthreads();
    }
}

// ============================================================================
extern "C" void kernel_launch(void* const* d_in, const int* in_sizes, int n_in,
                              void* d_out, int out_size)
{
    (void)in_sizes; (void)n_in; (void)out_size;
    const int*   q     = (const int*)  d_in[0];
    const int*   rsel  = (const int*)  d_in[1];
    const float* k_emb = (const float*)d_in[2];
    const float* v_emb = (const float*)d_in[3];
    const float* Mk    = (const float*)d_in[4];
    const float* Mv0   = (const float*)d_in[5];
    const float* f_W   = (const float*)d_in[6];
    const float* f_b   = (const float*)d_in[7];
    const float* e_W   = (const float*)d_in[8];
    const float* e_b   = (const float*)d_in[9];
    const float* a_W   = (const float*)d_in[10];
    const float* a_b   = (const float*)d_in[11];
    const float* ab_W  = (const float*)d_in[12];
    const float* ab_b  = (const float*)d_in[13];
    const float* df_W  = (const float*)d_in[14];
    const float* df_b  = (const float*)d_in[15];
    float* out = (float*)d_out;

    const int smA = (64 * 128 + 2 * 128 * 128 + 128 + 2048 + 2048 + 1024) * 4 + 32 * 4;
    const int smC = (128 * 256 + 4096 + 64) * 4;
    cudaFuncSetAttribute(kernelA, cudaFuncAttributeMaxDynamicSharedMemorySize, smA);
    cudaFuncSetAttribute(kernelC, cudaFuncAttributeMaxDynamicSharedMemorySize, smC);

    kernelA<<<148, 512, smA>>>(q, rsel, k_emb, v_emb, Mk, e_W, e_b,
                               a_W, a_b, df_W, df_b);
    kernelB<<<128, 256>>>(Mv0);
    kernelC<<<148, 512, smC>>>(f_W, f_b, ab_W, ab_b, out);
}